// round 1
// baseline (speedup 1.0000x reference)
#include <cuda_runtime.h>
#include <math.h>

#define NN   256
#define CZ   128
#define H    4
#define DH   32
#define NPOS (NN*NN)

// Scratch (device globals: allocation-free rule)
__device__ __align__(16) float g_xn[NPOS*CZ];
__device__ __align__(16) float g_q [NPOS*CZ];
__device__ __align__(16) float g_k [NPOS*CZ];
__device__ __align__(16) float g_v [NPOS*CZ];
__device__ __align__(16) float g_g [NPOS*CZ];
__device__ __align__(16) float g_o [NPOS*CZ];
__device__ __align__(16) float g_tri[H*NPOS];

// ---------------------------------------------------------------------------
// K1: LayerNorm over c_z (warp per position) + fused triangle bias
//     tri[h][pos] = dot(xn[pos,:], w_tri[h,:])
// ---------------------------------------------------------------------------
__global__ __launch_bounds__(256) void k_ln(
    const float* __restrict__ x,
    const float* __restrict__ ln_g,
    const float* __restrict__ ln_b,
    const float* __restrict__ w_tri)
{
    int warp = threadIdx.x >> 5;
    int lane = threadIdx.x & 31;
    int pos  = blockIdx.x * 8 + warp;          // grid = NPOS/8

    float4 v = *(const float4*)(x + (size_t)pos*CZ + lane*4);
    float s  = v.x + v.y + v.z + v.w;
    float ss = v.x*v.x + v.y*v.y + v.z*v.z + v.w*v.w;
    #pragma unroll
    for (int off = 16; off; off >>= 1) {
        s  += __shfl_xor_sync(0xffffffffu, s,  off);
        ss += __shfl_xor_sync(0xffffffffu, ss, off);
    }
    float mu  = s * (1.0f/CZ);
    float var = ss * (1.0f/CZ) - mu*mu;
    float rs  = rsqrtf(var + 1e-5f);

    float4 gg = *(const float4*)(ln_g + lane*4);
    float4 bb = *(const float4*)(ln_b + lane*4);
    float4 y;
    y.x = (v.x - mu)*rs*gg.x + bb.x;
    y.y = (v.y - mu)*rs*gg.y + bb.y;
    y.z = (v.z - mu)*rs*gg.z + bb.z;
    y.w = (v.w - mu)*rs*gg.w + bb.w;
    *(float4*)(g_xn + (size_t)pos*CZ + lane*4) = y;

    #pragma unroll
    for (int h = 0; h < H; h++) {
        float4 w = *(const float4*)(w_tri + h*CZ + lane*4);
        float d = y.x*w.x + y.y*w.y + y.z*w.z + y.w*w.w;
        #pragma unroll
        for (int off = 16; off; off >>= 1)
            d += __shfl_xor_sync(0xffffffffu, d, off);
        if (lane == 0) g_tri[h*NPOS + pos] = d;
    }
}

// ---------------------------------------------------------------------------
// K2: projections  y[pos][o] = sum_c xn[pos][c] * W[o][c]
//     Register-tiled GEMM: block = 64 positions x 128 outputs, K chunks of 32.
//     wi==3 (gate): y = sigmoid(y + bg[o])
// ---------------------------------------------------------------------------
__global__ __launch_bounds__(256) void k_proj(
    const float* __restrict__ wq, const float* __restrict__ wk,
    const float* __restrict__ wv, const float* __restrict__ wg,
    const float* __restrict__ bg)
{
    __shared__ float a_s[64][32];      // [pos][k]
    __shared__ float w_s[32][128];     // [k][out]

    int wi = blockIdx.y;
    const float* W = (wi==0) ? wq : (wi==1) ? wk : (wi==2) ? wv : wg;
    float* out     = (wi==0) ? g_q : (wi==1) ? g_k : (wi==2) ? g_v : g_g;

    int p0 = blockIdx.x * 64;
    int t  = threadIdx.x;
    int tx = t & 15;        // 16 -> 8 outputs each
    int ty = t >> 4;        // 16 -> 4 positions each

    float acc[4][8];
    #pragma unroll
    for (int m = 0; m < 4; m++)
        #pragma unroll
        for (int n = 0; n < 8; n++) acc[m][n] = 0.0f;

    for (int c0 = 0; c0 < CZ; c0 += 32) {
        __syncthreads();
        #pragma unroll
        for (int i = 0; i < 2; i++) {        // 64x32 floats = 512 float4
            int idx = t + i*256;
            int p = idx >> 3, c4 = idx & 7;
            float4 v = *(const float4*)(g_xn + (size_t)(p0+p)*CZ + c0 + c4*4);
            a_s[p][c4*4+0] = v.x; a_s[p][c4*4+1] = v.y;
            a_s[p][c4*4+2] = v.z; a_s[p][c4*4+3] = v.w;
        }
        #pragma unroll
        for (int i = 0; i < 4; i++) {        // 128x32 floats = 1024 float4
            int idx = t + i*256;
            int o = idx >> 3, c4 = idx & 7;
            float4 v = *(const float4*)(W + (size_t)o*CZ + c0 + c4*4);
            w_s[c4*4+0][o] = v.x; w_s[c4*4+1][o] = v.y;
            w_s[c4*4+2][o] = v.z; w_s[c4*4+3][o] = v.w;
        }
        __syncthreads();

        #pragma unroll
        for (int kk = 0; kk < 32; kk++) {
            float a[4];
            #pragma unroll
            for (int m = 0; m < 4; m++) a[m] = a_s[ty*4+m][kk];
            float4 b0 = *(const float4*)&w_s[kk][tx*8];
            float4 b1 = *(const float4*)&w_s[kk][tx*8+4];
            float b[8] = {b0.x,b0.y,b0.z,b0.w,b1.x,b1.y,b1.z,b1.w};
            #pragma unroll
            for (int m = 0; m < 4; m++)
                #pragma unroll
                for (int n = 0; n < 8; n++)
                    acc[m][n] += a[m]*b[n];
        }
    }

    #pragma unroll
    for (int m = 0; m < 4; m++) {
        int pos = p0 + ty*4 + m;
        #pragma unroll
        for (int n2 = 0; n2 < 2; n2++) {
            int ob = tx*8 + n2*4;
            float4 v;
            v.x = acc[m][n2*4+0]; v.y = acc[m][n2*4+1];
            v.z = acc[m][n2*4+2]; v.w = acc[m][n2*4+3];
            if (wi == 3) {
                v.x = 1.0f/(1.0f + __expf(-(v.x + bg[ob+0])));
                v.y = 1.0f/(1.0f + __expf(-(v.y + bg[ob+1])));
                v.z = 1.0f/(1.0f + __expf(-(v.z + bg[ob+2])));
                v.w = 1.0f/(1.0f + __expf(-(v.w + bg[ob+3])));
            }
            *(float4*)(out + (size_t)pos*CZ + ob) = v;
        }
    }
}

// ---------------------------------------------------------------------------
// K3: attention, block per (i, h). One q-row per thread, online softmax.
//     K/V staged through smem in two 128-row chunks. Gating fused in epilogue.
// ---------------------------------------------------------------------------
__global__ __launch_bounds__(256) void k_attn(const float* __restrict__ mask)
{
    __shared__ float k_s[128][32];
    __shared__ float v_s[128][32];
    __shared__ float mb_s[256];

    int i = blockIdx.x, h = blockIdx.y;
    int t = threadIdx.x;

    mb_s[t] = 1e9f * (mask[i*NN + t] - 1.0f);

    const float scale = 0.17677669529663687f;  // 1/sqrt(32)
    float q[DH];
    {
        const float* qp = g_q + ((size_t)(i*NN + t))*CZ + h*DH;
        #pragma unroll
        for (int u = 0; u < 8; u++) {
            float4 v = *(const float4*)(qp + u*4);
            q[u*4+0] = v.x*scale; q[u*4+1] = v.y*scale;
            q[u*4+2] = v.z*scale; q[u*4+3] = v.w*scale;
        }
    }
    const float* trirow = g_tri + (size_t)h*NPOS + t*NN;

    float m = -1e30f, l = 0.0f;
    float acc[DH];
    #pragma unroll
    for (int d = 0; d < DH; d++) acc[d] = 0.0f;

    for (int chunk = 0; chunk < 2; chunk++) {
        int jbase = chunk * 128;
        __syncthreads();
        #pragma unroll
        for (int it = 0; it < 4; it++) {
            int row = it*32 + (t >> 3);
            int c4  = t & 7;
            size_t base = ((size_t)(i*NN + jbase + row))*CZ + h*DH + c4*4;
            ((float4*)&k_s[row][0])[c4] = *(const float4*)(g_k + base);
            ((float4*)&v_s[row][0])[c4] = *(const float4*)(g_v + base);
        }
        __syncthreads();

        for (int jj = 0; jj < 128; jj++) {
            int j = jbase + jj;
            float s0 = 0.f, s1 = 0.f, s2 = 0.f, s3 = 0.f;
            #pragma unroll
            for (int d = 0; d < DH; d += 4) {
                s0 += q[d+0]*k_s[jj][d+0];
                s1 += q[d+1]*k_s[jj][d+1];
                s2 += q[d+2]*k_s[jj][d+2];
                s3 += q[d+3]*k_s[jj][d+3];
            }
            float s = ((s0+s1)+(s2+s3)) + mb_s[j] + trirow[j];
            if (s <= m) {
                float p = __expf(s - m);
                l += p;
                #pragma unroll
                for (int d = 0; d < DH; d++) acc[d] += p * v_s[jj][d];
            } else {
                float f = __expf(m - s);
                m = s;
                l = l*f + 1.0f;
                #pragma unroll
                for (int d = 0; d < DH; d++) acc[d] = acc[d]*f + v_s[jj][d];
            }
        }
    }

    float inv = 1.0f / l;
    size_t base = ((size_t)(i*NN + t))*CZ + h*DH;
    const float* gp = g_g + base;
    float* op = g_o + base;
    #pragma unroll
    for (int u = 0; u < 8; u++) {
        float4 gg = *(const float4*)(gp + u*4);
        float4 o4;
        o4.x = acc[u*4+0]*inv*gg.x;
        o4.y = acc[u*4+1]*inv*gg.y;
        o4.z = acc[u*4+2]*inv*gg.z;
        o4.w = acc[u*4+3]*inv*gg.w;
        *(float4*)(op + u*4) = o4;
    }
}

// ---------------------------------------------------------------------------
// K4: output projection  out[pos][o] = sum_e (o*g)[pos][e] * wo[o][e] + bo[o]
//     (gating already applied in K3 epilogue, so A = g_o directly)
// ---------------------------------------------------------------------------
__global__ __launch_bounds__(256) void k_out(
    const float* __restrict__ wo, const float* __restrict__ bo,
    float* __restrict__ out)
{
    __shared__ float a_s[64][32];
    __shared__ float w_s[32][128];

    int p0 = blockIdx.x * 64;
    int t  = threadIdx.x;
    int tx = t & 15;
    int ty = t >> 4;

    float acc[4][8];
    #pragma unroll
    for (int m = 0; m < 4; m++)
        #pragma unroll
        for (int n = 0; n < 8; n++) acc[m][n] = 0.0f;

    for (int c0 = 0; c0 < CZ; c0 += 32) {
        __syncthreads();
        #pragma unroll
        for (int i = 0; i < 2; i++) {
            int idx = t + i*256;
            int p = idx >> 3, c4 = idx & 7;
            float4 v = *(const float4*)(g_o + (size_t)(p0+p)*CZ + c0 + c4*4);
            a_s[p][c4*4+0] = v.x; a_s[p][c4*4+1] = v.y;
            a_s[p][c4*4+2] = v.z; a_s[p][c4*4+3] = v.w;
        }
        #pragma unroll
        for (int i = 0; i < 4; i++) {
            int idx = t + i*256;
            int o = idx >> 3, c4 = idx & 7;
            float4 v = *(const float4*)(wo + (size_t)o*CZ + c0 + c4*4);
            w_s[c4*4+0][o] = v.x; w_s[c4*4+1][o] = v.y;
            w_s[c4*4+2][o] = v.z; w_s[c4*4+3][o] = v.w;
        }
        __syncthreads();

        #pragma unroll
        for (int kk = 0; kk < 32; kk++) {
            float a[4];
            #pragma unroll
            for (int m = 0; m < 4; m++) a[m] = a_s[ty*4+m][kk];
            float4 b0 = *(const float4*)&w_s[kk][tx*8];
            float4 b1 = *(const float4*)&w_s[kk][tx*8+4];
            float b[8] = {b0.x,b0.y,b0.z,b0.w,b1.x,b1.y,b1.z,b1.w};
            #pragma unroll
            for (int m = 0; m < 4; m++)
                #pragma unroll
                for (int n = 0; n < 8; n++)
                    acc[m][n] += a[m]*b[n];
        }
    }

    #pragma unroll
    for (int m = 0; m < 4; m++) {
        int pos = p0 + ty*4 + m;
        #pragma unroll
        for (int n2 = 0; n2 < 2; n2++) {
            int ob = tx*8 + n2*4;
            float4 v;
            v.x = acc[m][n2*4+0] + bo[ob+0];
            v.y = acc[m][n2*4+1] + bo[ob+1];
            v.z = acc[m][n2*4+2] + bo[ob+2];
            v.w = acc[m][n2*4+3] + bo[ob+3];
            *(float4*)(out + (size_t)pos*CZ + ob) = v;
        }
    }
}

// ---------------------------------------------------------------------------
extern "C" void kernel_launch(void* const* d_in, const int* in_sizes, int n_in,
                              void* d_out, int out_size)
{
    const float* x     = (const float*)d_in[0];
    const float* mask  = (const float*)d_in[1];
    const float* ln_g  = (const float*)d_in[2];
    const float* ln_b  = (const float*)d_in[3];
    const float* w_tri = (const float*)d_in[4];
    const float* wq    = (const float*)d_in[5];
    const float* wk    = (const float*)d_in[6];
    const float* wv    = (const float*)d_in[7];
    const float* wg    = (const float*)d_in[8];
    const float* bg    = (const float*)d_in[9];
    const float* wo    = (const float*)d_in[10];
    const float* bo    = (const float*)d_in[11];
    float* out = (float*)d_out;

    k_ln  <<<NPOS/8, 256>>>(x, ln_g, ln_b, w_tri);
    k_proj<<<dim3(NPOS/64, 4), 256>>>(wq, wk, wv, wg, bg);
    k_attn<<<dim3(NN, H), 256>>>(mask);
    k_out <<<NPOS/64, 256>>>(wo, bo, out);
}

// round 3
// speedup vs baseline: 1.4482x; 1.4482x over previous
#include <cuda_runtime.h>
#include <math.h>

#define NN   256
#define CZ   128
#define H    4
#define DH   32
#define NPOS (NN*NN)

// Scratch (device globals: allocation-free rule).
// NOTE: referenced ONLY from device code — host cannot take their address.
__device__ __align__(16) float g_xn[NPOS*CZ];
__device__ __align__(16) float g_q [NPOS*CZ];
__device__ __align__(16) float g_k [NPOS*CZ];
__device__ __align__(16) float g_v [NPOS*CZ];
__device__ __align__(16) float g_g [NPOS*CZ];
__device__ __align__(16) float g_o [NPOS*CZ];
__device__ __align__(16) float g_tri[H*NPOS];

// ---------------------------------------------------------------------------
// K1: LayerNorm over c_z (warp per position) + fused triangle bias
// ---------------------------------------------------------------------------
__global__ __launch_bounds__(256) void k_ln(
    const float* __restrict__ x,
    const float* __restrict__ ln_g,
    const float* __restrict__ ln_b,
    const float* __restrict__ w_tri)
{
    int warp = threadIdx.x >> 5;
    int lane = threadIdx.x & 31;
    int pos  = blockIdx.x * 8 + warp;          // grid = NPOS/8

    float4 v = *(const float4*)(x + (size_t)pos*CZ + lane*4);
    float s  = v.x + v.y + v.z + v.w;
    float ss = v.x*v.x + v.y*v.y + v.z*v.z + v.w*v.w;
    #pragma unroll
    for (int off = 16; off; off >>= 1) {
        s  += __shfl_xor_sync(0xffffffffu, s,  off);
        ss += __shfl_xor_sync(0xffffffffu, ss, off);
    }
    float mu  = s * (1.0f/CZ);
    float var = ss * (1.0f/CZ) - mu*mu;
    float rs  = rsqrtf(var + 1e-5f);

    float4 gg = *(const float4*)(ln_g + lane*4);
    float4 bb = *(const float4*)(ln_b + lane*4);
    float4 y;
    y.x = (v.x - mu)*rs*gg.x + bb.x;
    y.y = (v.y - mu)*rs*gg.y + bb.y;
    y.z = (v.z - mu)*rs*gg.z + bb.z;
    y.w = (v.w - mu)*rs*gg.w + bb.w;
    *(float4*)(g_xn + (size_t)pos*CZ + lane*4) = y;

    #pragma unroll
    for (int h = 0; h < H; h++) {
        float4 w = *(const float4*)(w_tri + h*CZ + lane*4);
        float d = y.x*w.x + y.y*w.y + y.z*w.z + y.w*w.w;
        #pragma unroll
        for (int off = 16; off; off >>= 1)
            d += __shfl_xor_sync(0xffffffffu, d, off);
        if (lane == 0) g_tri[h*NPOS + pos] = d;
    }
}

// ---------------------------------------------------------------------------
// K2: generic GEMM  y[pos][o] = act( sum_c A[pos][c] * W[o][c] + bias )
//     Block tile 128 pos x 128 out, 8x8 per thread, K chunks of 16,
//     register-prefetch pipeline.
//     sel: 0..3 -> A=g_xn, out=g_{q,k,v,g} (sel 3 applies sigmoid+bias)
//     sel: 4    -> A=g_o,  out=extout (adds bias)
// ---------------------------------------------------------------------------
__global__ __launch_bounds__(256) void k_gemm(
    int sel,
    const float* __restrict__ W,
    const float* __restrict__ bias,
    float* __restrict__ extout)
{
    const float* A = (sel == 4) ? g_o : g_xn;
    float* out = (sel==0) ? g_q : (sel==1) ? g_k : (sel==2) ? g_v
               : (sel==3) ? g_g : extout;

    __shared__ float a_s[16][128];   // [k][pos]
    __shared__ float w_s[16][128];   // [k][out]

    int p0 = blockIdx.x * 128;
    int t  = threadIdx.x;
    int tx = t & 15;        // 16 groups -> 8 outputs each
    int ty = t >> 4;        // 16 groups -> 8 positions each

    float acc[8][8];
    #pragma unroll
    for (int m = 0; m < 8; m++)
        #pragma unroll
        for (int n = 0; n < 8; n++) acc[m][n] = 0.0f;

    // prefetch registers: 2 float4 each for A and W per chunk
    float4 pa[2], pw[2];
    #pragma unroll
    for (int i = 0; i < 2; i++) {
        int idx = t + i*256;                  // 0..511
        int p = idx >> 2, f = idx & 3;
        pa[i] = *(const float4*)(A + (size_t)(p0+p)*CZ + f*4);
        pw[i] = *(const float4*)(W + (size_t)p*CZ + f*4);   // p doubles as out row
    }

    for (int c0 = 0; c0 < CZ; c0 += 16) {
        // store prefetched chunk to smem
        #pragma unroll
        for (int i = 0; i < 2; i++) {
            int idx = t + i*256;
            int p = idx >> 2, f = idx & 3;
            a_s[f*4+0][p] = pa[i].x; a_s[f*4+1][p] = pa[i].y;
            a_s[f*4+2][p] = pa[i].z; a_s[f*4+3][p] = pa[i].w;
            w_s[f*4+0][p] = pw[i].x; w_s[f*4+1][p] = pw[i].y;
            w_s[f*4+2][p] = pw[i].z; w_s[f*4+3][p] = pw[i].w;
        }
        __syncthreads();

        // prefetch next chunk
        if (c0 + 16 < CZ) {
            #pragma unroll
            for (int i = 0; i < 2; i++) {
                int idx = t + i*256;
                int p = idx >> 2, f = idx & 3;
                pa[i] = *(const float4*)(A + (size_t)(p0+p)*CZ + c0 + 16 + f*4);
                pw[i] = *(const float4*)(W + (size_t)p*CZ + c0 + 16 + f*4);
            }
        }

        #pragma unroll
        for (int kk = 0; kk < 16; kk++) {
            float4 a0 = *(const float4*)&a_s[kk][ty*8];
            float4 a1 = *(const float4*)&a_s[kk][ty*8+4];
            float4 b0 = *(const float4*)&w_s[kk][tx*8];
            float4 b1 = *(const float4*)&w_s[kk][tx*8+4];
            float a[8] = {a0.x,a0.y,a0.z,a0.w,a1.x,a1.y,a1.z,a1.w};
            float b[8] = {b0.x,b0.y,b0.z,b0.w,b1.x,b1.y,b1.z,b1.w};
            #pragma unroll
            for (int m = 0; m < 8; m++)
                #pragma unroll
                for (int n = 0; n < 8; n++)
                    acc[m][n] += a[m]*b[n];
        }
        __syncthreads();
    }

    #pragma unroll
    for (int m = 0; m < 8; m++) {
        int pos = p0 + ty*8 + m;
        #pragma unroll
        for (int n2 = 0; n2 < 2; n2++) {
            int ob = tx*8 + n2*4;
            float4 v;
            v.x = acc[m][n2*4+0]; v.y = acc[m][n2*4+1];
            v.z = acc[m][n2*4+2]; v.w = acc[m][n2*4+3];
            if (sel == 3) {
                v.x = 1.0f/(1.0f + __expf(-(v.x + bias[ob+0])));
                v.y = 1.0f/(1.0f + __expf(-(v.y + bias[ob+1])));
                v.z = 1.0f/(1.0f + __expf(-(v.z + bias[ob+2])));
                v.w = 1.0f/(1.0f + __expf(-(v.w + bias[ob+3])));
            } else if (sel == 4) {
                v.x += bias[ob+0]; v.y += bias[ob+1];
                v.z += bias[ob+2]; v.w += bias[ob+3];
            }
            *(float4*)(out + (size_t)pos*CZ + ob) = v;
        }
    }
}

// ---------------------------------------------------------------------------
// K3: attention, block per (i, h). One q-row per thread.
//     Chunked (16-key) online softmax: one rescale + max-tree per chunk.
// ---------------------------------------------------------------------------
__global__ __launch_bounds__(256) void k_attn(const float* __restrict__ mask)
{
    __shared__ float k_s[128][32];
    __shared__ float v_s[128][32];
    __shared__ float mb_s[256];

    int i = blockIdx.x, h = blockIdx.y;
    int t = threadIdx.x;

    mb_s[t] = 1e9f * (mask[i*NN + t] - 1.0f);

    const float scale = 0.17677669529663687f;  // 1/sqrt(32)
    float q[DH];
    {
        const float* qp = g_q + ((size_t)(i*NN + t))*CZ + h*DH;
        #pragma unroll
        for (int u = 0; u < 8; u++) {
            float4 v = *(const float4*)(qp + u*4);
            q[u*4+0] = v.x*scale; q[u*4+1] = v.y*scale;
            q[u*4+2] = v.z*scale; q[u*4+3] = v.w*scale;
        }
    }
    const float* trirow = g_tri + (size_t)h*NPOS + t*NN;   // tri[h][q=t][:]

    float m = -1e30f, l = 0.0f;
    float acc[DH];
    #pragma unroll
    for (int d = 0; d < DH; d++) acc[d] = 0.0f;

    for (int chunk = 0; chunk < 2; chunk++) {
        int jbase = chunk * 128;
        __syncthreads();
        #pragma unroll
        for (int it = 0; it < 4; it++) {
            int row = it*32 + (t >> 3);
            int c4  = t & 7;
            size_t base = ((size_t)(i*NN + jbase + row))*CZ + h*DH + c4*4;
            ((float4*)&k_s[row][0])[c4] = *(const float4*)(g_k + base);
            ((float4*)&v_s[row][0])[c4] = *(const float4*)(g_v + base);
        }
        __syncthreads();

        for (int jj0 = 0; jj0 < 128; jj0 += 16) {
            float tr[16];
            #pragma unroll
            for (int u4 = 0; u4 < 4; u4++) {
                float4 tv = *(const float4*)(trirow + jbase + jj0 + u4*4);
                tr[u4*4+0] = tv.x; tr[u4*4+1] = tv.y;
                tr[u4*4+2] = tv.z; tr[u4*4+3] = tv.w;
            }

            float s[16];
            #pragma unroll
            for (int u = 0; u < 16; u++) {
                int jj = jj0 + u;
                float s0 = 0.f, s1 = 0.f, s2 = 0.f, s3 = 0.f;
                #pragma unroll
                for (int d = 0; d < DH; d += 4) {
                    s0 += q[d+0]*k_s[jj][d+0];
                    s1 += q[d+1]*k_s[jj][d+1];
                    s2 += q[d+2]*k_s[jj][d+2];
                    s3 += q[d+3]*k_s[jj][d+3];
                }
                s[u] = ((s0+s1)+(s2+s3)) + mb_s[jbase+jj] + tr[u];
            }

            float cm = s[0];
            #pragma unroll
            for (int u = 1; u < 16; u++) cm = fmaxf(cm, s[u]);
            float mnew = fmaxf(m, cm);
            float f = __expf(m - mnew);

            l *= f;
            #pragma unroll
            for (int d = 0; d < DH; d++) acc[d] *= f;

            #pragma unroll
            for (int u = 0; u < 16; u++) {
                float p = __expf(s[u] - mnew);
                l += p;
                int jj = jj0 + u;
                #pragma unroll
                for (int d = 0; d < DH; d += 4) {
                    float4 vv = *(const float4*)&v_s[jj][d];
                    acc[d+0] += p*vv.x; acc[d+1] += p*vv.y;
                    acc[d+2] += p*vv.z; acc[d+3] += p*vv.w;
                }
            }
            m = mnew;
        }
    }

    float inv = 1.0f / l;
    size_t base = ((size_t)(i*NN + t))*CZ + h*DH;
    const float* gp = g_g + base;
    float* op = g_o + base;
    #pragma unroll
    for (int u = 0; u < 8; u++) {
        float4 gg = *(const float4*)(gp + u*4);
        float4 o4;
        o4.x = acc[u*4+0]*inv*gg.x;
        o4.y = acc[u*4+1]*inv*gg.y;
        o4.z = acc[u*4+2]*inv*gg.z;
        o4.w = acc[u*4+3]*inv*gg.w;
        *(float4*)(op + u*4) = o4;
    }
}

// ---------------------------------------------------------------------------
extern "C" void kernel_launch(void* const* d_in, const int* in_sizes, int n_in,
                              void* d_out, int out_size)
{
    const float* x     = (const float*)d_in[0];
    const float* mask  = (const float*)d_in[1];
    const float* ln_g  = (const float*)d_in[2];
    const float* ln_b  = (const float*)d_in[3];
    const float* w_tri = (const float*)d_in[4];
    const float* wq    = (const float*)d_in[5];
    const float* wk    = (const float*)d_in[6];
    const float* wv    = (const float*)d_in[7];
    const float* wg    = (const float*)d_in[8];
    const float* bg    = (const float*)d_in[9];
    const float* wo    = (const float*)d_in[10];
    const float* bo    = (const float*)d_in[11];
    float* out = (float*)d_out;

    k_ln  <<<NPOS/8, 256>>>(x, ln_g, ln_b, w_tri);
    k_gemm<<<NPOS/128, 256>>>(0, wq, nullptr, nullptr);
    k_gemm<<<NPOS/128, 256>>>(1, wk, nullptr, nullptr);
    k_gemm<<<NPOS/128, 256>>>(2, wv, nullptr, nullptr);
    k_gemm<<<NPOS/128, 256>>>(3, wg, bg,      nullptr);
    k_attn<<<dim3(NN, H), 256>>>(mask);
    k_gemm<<<NPOS/128, 256>>>(4, wo, bo, out);
}